// round 1
// baseline (speedup 1.0000x reference)
#include <cuda_runtime.h>

#define NNODE   100000
#define NEDGE   3200000
#define DIM     300
#define HID     16
#define NG      5
#define TOT     (NG*NNODE)      // 500000
#define TOTEDGE (NG*NEDGE)      // 16000000

// -------- scratch (no allocations allowed; __device__ globals) --------
__device__ __align__(16) float g_scr[TOT*HID];   // g = (emb@W1)*dis[n], 32MB
__device__ int   elist_scr[TOTEDGE];             // CSR-by-dst src lists, 64MB
__device__ int   deg_scr[TOT];
__device__ int   off_scr[TOT];
__device__ int   cnt_scr[TOT];
__device__ float dis_scr[TOT];
__device__ float c_scr[TOT];                     // c[s] = sum over out-edges of dis[dst]
__device__ float score_scr[NG];
__device__ int   bsum_scr[512];
__device__ int   bpre_scr[512];
__device__ int   d_is64;

#define SCAN_BLK 489   // ceil(500000/1024)

// -------- detect whether edge_index is int64 or int32 (jax x64 trap) --------
__global__ void detect_kernel(const void* ei) {
    if (threadIdx.x == 0) {
        const unsigned long long* p = (const unsigned long long*)ei;
        int ok = 1;
        for (int i = 0; i < 64; ++i)
            if (p[i] >> 32) ok = 0;   // int32 data -> high word is another index (!=0 w.h.p.)
        d_is64 = ok;
    }
}

__device__ __forceinline__ void load_edge(const void* ei, int is64, long long base,
                                          int e, int& src, int& dst) {
    if (is64) {
        const long long* p = (const long long*)ei;
        src = (int)p[base + e];
        dst = (int)p[base + NEDGE + e];
    } else {
        const int* p = (const int*)ei;
        src = p[base + e];
        dst = p[base + NEDGE + e];
    }
}

// -------- init: zero the accumulators that get atomically updated --------
__global__ void init_kernel() {
    int i = blockIdx.x * blockDim.x + threadIdx.x;
    if (i < TOT) { deg_scr[i] = 0; cnt_scr[i] = 0; c_scr[i] = 0.f; }
    if (i < NG)  score_scr[i] = 0.f;
}

// -------- degree histogram (in-degree at dst) --------
__global__ void deg_kernel(const void* __restrict__ ei) {
    int e = blockIdx.x * blockDim.x + threadIdx.x;
    if (e >= NEDGE) return;
    int gy = blockIdx.y;
    int is64 = d_is64;
    long long base = (long long)gy * 2 * NEDGE;
    int src, dst;
    load_edge(ei, is64, base, e, src, dst);
    atomicAdd(&deg_scr[gy * NNODE + dst], 1);
}

// -------- dis = rsqrt(deg+1)  (self-loop) --------
__global__ void dis_kernel() {
    int i = blockIdx.x * blockDim.x + threadIdx.x;
    if (i < TOT) dis_scr[i] = rsqrtf((float)deg_scr[i] + 1.0f);
}

// -------- exclusive scan of deg -> off (3 kernels) --------
__global__ void scan_a_kernel() {
    int tid = threadIdx.x;
    int i0 = (blockIdx.x * 256 + tid) * 4;
    int s = 0;
    #pragma unroll
    for (int r = 0; r < 4; ++r)
        if (i0 + r < TOT) s += deg_scr[i0 + r];
    // block reduce
    #pragma unroll
    for (int off = 16; off; off >>= 1) s += __shfl_down_sync(0xffffffffu, s, off);
    __shared__ int ws[8];
    if ((tid & 31) == 0) ws[tid >> 5] = s;
    __syncthreads();
    if (tid == 0) {
        int t = 0;
        #pragma unroll
        for (int w = 0; w < 8; ++w) t += ws[w];
        bsum_scr[blockIdx.x] = t;
    }
}

__global__ void scan_b_kernel() {
    __shared__ int sh[512];
    int tid = threadIdx.x;
    int v = (tid < SCAN_BLK) ? bsum_scr[tid] : 0;
    sh[tid] = v;
    int orig = v;
    for (int off = 1; off < 512; off <<= 1) {
        __syncthreads();
        int u = (tid >= off) ? sh[tid - off] : 0;
        __syncthreads();
        sh[tid] += u;
    }
    __syncthreads();
    if (tid < SCAN_BLK) bpre_scr[tid] = sh[tid] - orig;   // exclusive
}

__global__ void scan_c_kernel() {
    int tid = threadIdx.x;
    int lane = tid & 31, wid = tid >> 5;
    int i0 = (blockIdx.x * 256 + tid) * 4;
    int v[4];
    #pragma unroll
    for (int r = 0; r < 4; ++r)
        v[r] = (i0 + r < TOT) ? deg_scr[i0 + r] : 0;
    int tsum = v[0] + v[1] + v[2] + v[3];
    int incl = tsum;
    #pragma unroll
    for (int off = 1; off < 32; off <<= 1) {
        int u = __shfl_up_sync(0xffffffffu, incl, off);
        if (lane >= off) incl += u;
    }
    __shared__ int wsum[8], wbase[8];
    if (lane == 31) wsum[wid] = incl;
    __syncthreads();
    if (tid == 0) {
        int r = 0;
        #pragma unroll
        for (int w = 0; w < 8; ++w) { wbase[w] = r; r += wsum[w]; }
    }
    __syncthreads();
    int run = bpre_scr[blockIdx.x] + wbase[wid] + (incl - tsum);
    #pragma unroll
    for (int r = 0; r < 4; ++r) {
        if (i0 + r < TOT) off_scr[i0 + r] = run;
        run += v[r];
    }
}

// -------- GEMM: g[n][k] = (sum_j emb[n][j]*W1[j][k]) * dis[n] --------
// 256 threads, 512 nodes/block, 2 nodes/thread, j-chunks of 30, smem-transposed A.
#define JC 30
#define SA_STRIDE 513
#define SW_FLOATS (DIM*HID)          // 4800
#define SA_FLOATS (JC*SA_STRIDE)     // 15390
#define GEMM_SMEM ((SW_FLOATS + SA_FLOATS) * 4)

#define STEP(ACC, A) \
    ACC[0]=fmaf(A,w0.x,ACC[0]);  ACC[1]=fmaf(A,w0.y,ACC[1]);  \
    ACC[2]=fmaf(A,w0.z,ACC[2]);  ACC[3]=fmaf(A,w0.w,ACC[3]);  \
    ACC[4]=fmaf(A,w1.x,ACC[4]);  ACC[5]=fmaf(A,w1.y,ACC[5]);  \
    ACC[6]=fmaf(A,w1.z,ACC[6]);  ACC[7]=fmaf(A,w1.w,ACC[7]);  \
    ACC[8]=fmaf(A,w2.x,ACC[8]);  ACC[9]=fmaf(A,w2.y,ACC[9]);  \
    ACC[10]=fmaf(A,w2.z,ACC[10]);ACC[11]=fmaf(A,w2.w,ACC[11]);\
    ACC[12]=fmaf(A,w3.x,ACC[12]);ACC[13]=fmaf(A,w3.y,ACC[13]);\
    ACC[14]=fmaf(A,w3.z,ACC[14]);ACC[15]=fmaf(A,w3.w,ACC[15]);

__global__ void __launch_bounds__(256) gemm_kernel(const float* __restrict__ emb,
                                                   const float* __restrict__ W1) {
    extern __shared__ float sm[];
    float* sW = sm;                // 4800 floats
    float* sA = sm + SW_FLOATS;    // [JC][513]
    int tid = threadIdx.x;
    int nbase = blockIdx.x * 512;

    for (int idx = tid; idx < SW_FLOATS; idx += 256) sW[idx] = W1[idx];

    float acc0[16], acc1[16];
    #pragma unroll
    for (int k = 0; k < 16; ++k) { acc0[k] = 0.f; acc1[k] = 0.f; }

    for (int c = 0; c < 10; ++c) {
        int j0 = c * JC;
        __syncthreads();
        // load 512 nodes x 30 j as float2, store transposed [j][node]
        #pragma unroll
        for (int it = 0; it < 30; ++it) {
            int idx = it * 256 + tid;
            int n = idx / 15;
            int jp = idx - n * 15;
            int gn = nbase + n;
            float2 v = make_float2(0.f, 0.f);
            if (gn < TOT)
                v = *(const float2*)(emb + (size_t)gn * DIM + j0 + 2 * jp);
            sA[(2 * jp)     * SA_STRIDE + n] = v.x;
            sA[(2 * jp + 1) * SA_STRIDE + n] = v.y;
        }
        __syncthreads();
        #pragma unroll
        for (int jl = 0; jl < JC; ++jl) {
            float a0 = sA[jl * SA_STRIDE + tid];
            float a1 = sA[jl * SA_STRIDE + 256 + tid];
            const float4* wr = (const float4*)(sW + (j0 + jl) * HID);
            float4 w0 = wr[0], w1 = wr[1], w2 = wr[2], w3 = wr[3];
            STEP(acc0, a0)
            STEP(acc1, a1)
        }
    }

    int gn0 = nbase + tid;
    int gn1 = nbase + 256 + tid;
    if (gn0 < TOT) {
        float dd = dis_scr[gn0];
        float4* o = (float4*)(g_scr + (size_t)gn0 * HID);
        o[0] = make_float4(acc0[0]*dd,  acc0[1]*dd,  acc0[2]*dd,  acc0[3]*dd);
        o[1] = make_float4(acc0[4]*dd,  acc0[5]*dd,  acc0[6]*dd,  acc0[7]*dd);
        o[2] = make_float4(acc0[8]*dd,  acc0[9]*dd,  acc0[10]*dd, acc0[11]*dd);
        o[3] = make_float4(acc0[12]*dd, acc0[13]*dd, acc0[14]*dd, acc0[15]*dd);
    }
    if (gn1 < TOT) {
        float dd = dis_scr[gn1];
        float4* o = (float4*)(g_scr + (size_t)gn1 * HID);
        o[0] = make_float4(acc1[0]*dd,  acc1[1]*dd,  acc1[2]*dd,  acc1[3]*dd);
        o[1] = make_float4(acc1[4]*dd,  acc1[5]*dd,  acc1[6]*dd,  acc1[7]*dd);
        o[2] = make_float4(acc1[8]*dd,  acc1[9]*dd,  acc1[10]*dd, acc1[11]*dd);
        o[3] = make_float4(acc1[12]*dd, acc1[13]*dd, acc1[14]*dd, acc1[15]*dd);
    }
}

// -------- fill CSR slots + accumulate c[src] += dis[dst] --------
__global__ void fill_kernel(const void* __restrict__ ei) {
    int e = blockIdx.x * blockDim.x + threadIdx.x;
    if (e >= NEDGE) return;
    int gy = blockIdx.y;
    int is64 = d_is64;
    long long base = (long long)gy * 2 * NEDGE;
    int src, dst;
    load_edge(ei, is64, base, e, src, dst);
    int s = gy * NNODE + src;
    int d = gy * NNODE + dst;
    int pos = off_scr[d] + atomicAdd(&cnt_scr[d], 1);
    elist_scr[pos] = s;
    atomicAdd(&c_scr[s], dis_scr[d]);
}

// -------- gather + layer1 epilogue + layer2 dot + score reduce --------
// warp per node; 16 lanes = 16 hidden dims; 2 edges per warp iteration.
__global__ void __launch_bounds__(256) gather_kernel(const float* __restrict__ b1,
                                                     const float* __restrict__ W2) {
    int wid  = threadIdx.x >> 5;
    int lane = threadIdx.x & 31;
    int n = blockIdx.x * 8 + wid;            // blocks never straddle graphs: 100000 % 8 == 0
    int gidx = blockIdx.x / (NNODE / 8);     // graph id

    int start = off_scr[n];
    int cnt   = deg_scr[n];
    int k = lane & 15;

    float acc = 0.f;
    for (int i = (lane >> 4); i < cnt; i += 2) {
        int s = elist_scr[start + i];
        acc += g_scr[(size_t)s * HID + k];
    }
    acc += __shfl_down_sync(0xffffffffu, acc, 16);

    float dd = dis_scr[n];
    float h2 = 0.f;
    if (lane < 16) {
        float gk = g_scr[(size_t)n * HID + k];
        float h = fmaxf(fmaf(dd, acc + gk, __ldg(&b1[k])), 0.f);
        h2 = h * __ldg(&W2[k]);
    }
    #pragma unroll
    for (int off = 8; off; off >>= 1) h2 += __shfl_down_sync(0xffffffffu, h2, off);

    __shared__ float part[8];
    if (lane == 0) part[wid] = h2 * dd * (c_scr[n] + dd);
    __syncthreads();
    if (threadIdx.x == 0) {
        float t = 0.f;
        #pragma unroll
        for (int w = 0; w < 8; ++w) t += part[w];
        atomicAdd(&score_scr[gidx], t);
    }
}

// -------- softmax over 5 graph scores --------
__global__ void softmax_kernel(const float* __restrict__ b2, float* __restrict__ out) {
    if (threadIdx.x == 0) {
        float s[NG], m = -1e30f;
        for (int g = 0; g < NG; ++g) {
            s[g] = score_scr[g] * (1.0f / (float)NNODE) + b2[0];
            m = fmaxf(m, s[g]);
        }
        float sum = 0.f, e[NG];
        for (int g = 0; g < NG; ++g) { e[g] = expf(s[g] - m); sum += e[g]; }
        for (int g = 0; g < NG; ++g) out[g] = e[g] / sum;
    }
}

extern "C" void kernel_launch(void* const* d_in, const int* in_sizes, int n_in,
                              void* d_out, int out_size) {
    const float* emb = (const float*)d_in[0];
    const void*  ei  = d_in[1];
    const float* W1  = (const float*)d_in[2];
    const float* b1  = (const float*)d_in[3];
    const float* W2  = (const float*)d_in[4];
    const float* b2  = (const float*)d_in[5];
    float* out = (float*)d_out;

    cudaFuncSetAttribute((const void*)gemm_kernel,
                         cudaFuncAttributeMaxDynamicSharedMemorySize, GEMM_SMEM);

    detect_kernel<<<1, 32>>>(ei);
    init_kernel<<<(TOT + 255) / 256, 256>>>();

    dim3 eg((NEDGE + 255) / 256, NG);
    deg_kernel<<<eg, 256>>>(ei);

    dis_kernel<<<(TOT + 255) / 256, 256>>>();

    scan_a_kernel<<<SCAN_BLK, 256>>>();
    scan_b_kernel<<<1, 512>>>();
    scan_c_kernel<<<SCAN_BLK, 256>>>();

    fill_kernel<<<eg, 256>>>(ei);

    gemm_kernel<<<(TOT + 511) / 512, 256, GEMM_SMEM>>>(emb, W1);

    gather_kernel<<<TOT / 8, 256>>>(b1, W2);

    softmax_kernel<<<1, 32>>>(b2, out);
}

// round 2
// speedup vs baseline: 1.0362x; 1.0362x over previous
#include <cuda_runtime.h>

#define NNODE   100000
#define NEDGE   3200000
#define DIM     300
#define HID     16
#define NG      5
#define TOT     (NG*NNODE)      // 500000
#define TOTEDGE (NG*NEDGE)      // 16000000

// -------- scratch (no allocations allowed; __device__ globals) --------
__device__ __align__(16) float g_scr[TOT*HID];   // g = (emb@W1)*dis[n], 32MB
__device__ int   elist_scr[TOTEDGE];             // CSR-by-dst src lists, 64MB
__device__ int   deg_scr[TOT];
__device__ int   off_scr[TOT];
__device__ int   cnt_scr[TOT];                   // initialized to off by scan_c; bumped in fill
__device__ float dis_scr[TOT];
__device__ float c_scr[TOT];                     // c[s] = sum over out-edges of dis[dst]
__device__ float score_scr[NG];
__device__ int   bsum_scr[512];
__device__ int   bpre_scr[512];
__device__ int   d_is64;

#define SCAN_BLK 489   // ceil(500000/1024)

// -------- detect whether edge_index is int64 or int32 (jax x64 trap) --------
__global__ void detect_kernel(const void* ei) {
    if (threadIdx.x == 0) {
        const unsigned long long* p = (const unsigned long long*)ei;
        int ok = 1;
        for (int i = 0; i < 64; ++i)
            if (p[i] >> 32) ok = 0;   // int32 data -> high word is another index (!=0 w.h.p.)
        d_is64 = ok;
    }
}

// -------- init: zero the accumulators that get atomically updated --------
__global__ void init_kernel() {
    int i = blockIdx.x * blockDim.x + threadIdx.x;
    if (i < TOT) { deg_scr[i] = 0; c_scr[i] = 0.f; }
    if (i < NG)  score_scr[i] = 0.f;
}

// -------- degree histogram (dst only, 4 edges/thread, 16B loads) --------
__global__ void deg_kernel(const void* __restrict__ ei) {
    int e0 = (blockIdx.x * blockDim.x + threadIdx.x) * 4;
    if (e0 >= NEDGE) return;
    int gy = blockIdx.y;
    int dbase = gy * NNODE;
    int d0, d1, d2, d3;
    if (d_is64) {
        const longlong2* p = (const longlong2*)
            ((const long long*)ei + (long long)gy * 2 * NEDGE + NEDGE + e0);
        longlong2 a = p[0], b = p[1];
        d0 = (int)a.x; d1 = (int)a.y; d2 = (int)b.x; d3 = (int)b.y;
    } else {
        int4 v = *(const int4*)((const int*)ei + (long long)gy * 2 * NEDGE + NEDGE + e0);
        d0 = v.x; d1 = v.y; d2 = v.z; d3 = v.w;
    }
    atomicAdd(&deg_scr[dbase + d0], 1);
    atomicAdd(&deg_scr[dbase + d1], 1);
    atomicAdd(&deg_scr[dbase + d2], 1);
    atomicAdd(&deg_scr[dbase + d3], 1);
}

// -------- exclusive scan of deg -> off (3 kernels); scan_c also emits dis & cnt --------
__global__ void scan_a_kernel() {
    int tid = threadIdx.x;
    int i0 = (blockIdx.x * 256 + tid) * 4;
    int s = 0;
    #pragma unroll
    for (int r = 0; r < 4; ++r)
        if (i0 + r < TOT) s += deg_scr[i0 + r];
    #pragma unroll
    for (int off = 16; off; off >>= 1) s += __shfl_down_sync(0xffffffffu, s, off);
    __shared__ int ws[8];
    if ((tid & 31) == 0) ws[tid >> 5] = s;
    __syncthreads();
    if (tid == 0) {
        int t = 0;
        #pragma unroll
        for (int w = 0; w < 8; ++w) t += ws[w];
        bsum_scr[blockIdx.x] = t;
    }
}

__global__ void scan_b_kernel() {
    __shared__ int sh[512];
    int tid = threadIdx.x;
    int v = (tid < SCAN_BLK) ? bsum_scr[tid] : 0;
    sh[tid] = v;
    int orig = v;
    for (int off = 1; off < 512; off <<= 1) {
        __syncthreads();
        int u = (tid >= off) ? sh[tid - off] : 0;
        __syncthreads();
        sh[tid] += u;
    }
    __syncthreads();
    if (tid < SCAN_BLK) bpre_scr[tid] = sh[tid] - orig;   // exclusive
}

__global__ void scan_c_kernel() {
    int tid = threadIdx.x;
    int lane = tid & 31, wid = tid >> 5;
    int i0 = (blockIdx.x * 256 + tid) * 4;
    int v[4];
    #pragma unroll
    for (int r = 0; r < 4; ++r)
        v[r] = (i0 + r < TOT) ? deg_scr[i0 + r] : 0;
    int tsum = v[0] + v[1] + v[2] + v[3];
    int incl = tsum;
    #pragma unroll
    for (int off = 1; off < 32; off <<= 1) {
        int u = __shfl_up_sync(0xffffffffu, incl, off);
        if (lane >= off) incl += u;
    }
    __shared__ int wsum[8], wbase[8];
    if (lane == 31) wsum[wid] = incl;
    __syncthreads();
    if (tid == 0) {
        int r = 0;
        #pragma unroll
        for (int w = 0; w < 8; ++w) { wbase[w] = r; r += wsum[w]; }
    }
    __syncthreads();
    int run = bpre_scr[blockIdx.x] + wbase[wid] + (incl - tsum);
    #pragma unroll
    for (int r = 0; r < 4; ++r) {
        if (i0 + r < TOT) {
            off_scr[i0 + r] = run;
            cnt_scr[i0 + r] = run;                         // fill bumps this copy
            dis_scr[i0 + r] = rsqrtf((float)v[r] + 1.0f);  // self-loop degree
        }
        run += v[r];
    }
}

// -------- GEMM: g[n][k] = (sum_j emb[n][j]*W1[j][k]) * dis[n] --------
#define JC 30
#define SA_STRIDE 513
#define SW_FLOATS (DIM*HID)          // 4800
#define SA_FLOATS (JC*SA_STRIDE)     // 15390
#define GEMM_SMEM ((SW_FLOATS + SA_FLOATS) * 4)

#define STEP(ACC, A) \
    ACC[0]=fmaf(A,w0.x,ACC[0]);  ACC[1]=fmaf(A,w0.y,ACC[1]);  \
    ACC[2]=fmaf(A,w0.z,ACC[2]);  ACC[3]=fmaf(A,w0.w,ACC[3]);  \
    ACC[4]=fmaf(A,w1.x,ACC[4]);  ACC[5]=fmaf(A,w1.y,ACC[5]);  \
    ACC[6]=fmaf(A,w1.z,ACC[6]);  ACC[7]=fmaf(A,w1.w,ACC[7]);  \
    ACC[8]=fmaf(A,w2.x,ACC[8]);  ACC[9]=fmaf(A,w2.y,ACC[9]);  \
    ACC[10]=fmaf(A,w2.z,ACC[10]);ACC[11]=fmaf(A,w2.w,ACC[11]);\
    ACC[12]=fmaf(A,w3.x,ACC[12]);ACC[13]=fmaf(A,w3.y,ACC[13]);\
    ACC[14]=fmaf(A,w3.z,ACC[14]);ACC[15]=fmaf(A,w3.w,ACC[15]);

__global__ void __launch_bounds__(256) gemm_kernel(const float* __restrict__ emb,
                                                   const float* __restrict__ W1) {
    extern __shared__ float sm[];
    float* sW = sm;                // 4800 floats
    float* sA = sm + SW_FLOATS;    // [JC][513]
    int tid = threadIdx.x;
    int nbase = blockIdx.x * 512;

    for (int idx = tid; idx < SW_FLOATS; idx += 256) sW[idx] = W1[idx];

    float acc0[16], acc1[16];
    #pragma unroll
    for (int k = 0; k < 16; ++k) { acc0[k] = 0.f; acc1[k] = 0.f; }

    for (int c = 0; c < 10; ++c) {
        int j0 = c * JC;
        __syncthreads();
        #pragma unroll
        for (int it = 0; it < 30; ++it) {
            int idx = it * 256 + tid;
            int n = idx / 15;
            int jp = idx - n * 15;
            int gn = nbase + n;
            float2 v = make_float2(0.f, 0.f);
            if (gn < TOT)
                v = *(const float2*)(emb + (size_t)gn * DIM + j0 + 2 * jp);
            sA[(2 * jp)     * SA_STRIDE + n] = v.x;
            sA[(2 * jp + 1) * SA_STRIDE + n] = v.y;
        }
        __syncthreads();
        #pragma unroll
        for (int jl = 0; jl < JC; ++jl) {
            float a0 = sA[jl * SA_STRIDE + tid];
            float a1 = sA[jl * SA_STRIDE + 256 + tid];
            const float4* wr = (const float4*)(sW + (j0 + jl) * HID);
            float4 w0 = wr[0], w1 = wr[1], w2 = wr[2], w3 = wr[3];
            STEP(acc0, a0)
            STEP(acc1, a1)
        }
    }

    int gn0 = nbase + tid;
    int gn1 = nbase + 256 + tid;
    if (gn0 < TOT) {
        float dd = dis_scr[gn0];
        float4* o = (float4*)(g_scr + (size_t)gn0 * HID);
        o[0] = make_float4(acc0[0]*dd,  acc0[1]*dd,  acc0[2]*dd,  acc0[3]*dd);
        o[1] = make_float4(acc0[4]*dd,  acc0[5]*dd,  acc0[6]*dd,  acc0[7]*dd);
        o[2] = make_float4(acc0[8]*dd,  acc0[9]*dd,  acc0[10]*dd, acc0[11]*dd);
        o[3] = make_float4(acc0[12]*dd, acc0[13]*dd, acc0[14]*dd, acc0[15]*dd);
    }
    if (gn1 < TOT) {
        float dd = dis_scr[gn1];
        float4* o = (float4*)(g_scr + (size_t)gn1 * HID);
        o[0] = make_float4(acc1[0]*dd,  acc1[1]*dd,  acc1[2]*dd,  acc1[3]*dd);
        o[1] = make_float4(acc1[4]*dd,  acc1[5]*dd,  acc1[6]*dd,  acc1[7]*dd);
        o[2] = make_float4(acc1[8]*dd,  acc1[9]*dd,  acc1[10]*dd, acc1[11]*dd);
        o[3] = make_float4(acc1[12]*dd, acc1[13]*dd, acc1[14]*dd, acc1[15]*dd);
    }
}

// -------- fill CSR slots + accumulate c[src] += dis[dst]; 4 edges/thread --------
__global__ void fill_kernel(const void* __restrict__ ei) {
    int e0 = (blockIdx.x * blockDim.x + threadIdx.x) * 4;
    if (e0 >= NEDGE) return;
    int gy = blockIdx.y;
    int nb = gy * NNODE;
    int s[4], d[4];
    if (d_is64) {
        const long long* base = (const long long*)ei + (long long)gy * 2 * NEDGE;
        longlong2 sa = *(const longlong2*)(base + e0);
        longlong2 sb = *(const longlong2*)(base + e0 + 2);
        longlong2 da = *(const longlong2*)(base + NEDGE + e0);
        longlong2 db = *(const longlong2*)(base + NEDGE + e0 + 2);
        s[0]=(int)sa.x; s[1]=(int)sa.y; s[2]=(int)sb.x; s[3]=(int)sb.y;
        d[0]=(int)da.x; d[1]=(int)da.y; d[2]=(int)db.x; d[3]=(int)db.y;
    } else {
        const int* base = (const int*)ei + (long long)gy * 2 * NEDGE;
        int4 sv = *(const int4*)(base + e0);
        int4 dv = *(const int4*)(base + NEDGE + e0);
        s[0]=sv.x; s[1]=sv.y; s[2]=sv.z; s[3]=sv.w;
        d[0]=dv.x; d[1]=dv.y; d[2]=dv.z; d[3]=dv.w;
    }
    #pragma unroll
    for (int r = 0; r < 4; ++r) {
        int ds = nb + d[r];
        int pos = atomicAdd(&cnt_scr[ds], 1);
        elist_scr[pos] = nb + s[r];
        atomicAdd(&c_scr[nb + s[r]], dis_scr[ds]);
    }
}

// -------- gather + layer1 epilogue + layer2 dot + score reduce --------
// warp per node; 32 src indices loaded coalesced into regs, shfl-broadcast;
// 16 lanes = hidden dims, 2 half-warps process interleaved edges, 4 loads in flight.
__global__ void __launch_bounds__(256) gather_kernel(const float* __restrict__ b1,
                                                     const float* __restrict__ W2) {
    int wid  = threadIdx.x >> 5;
    int lane = threadIdx.x & 31;
    int n = blockIdx.x * 8 + wid;            // blocks never straddle graphs: 100000 % 8 == 0
    int gidx = blockIdx.x / (NNODE / 8);

    int start = off_scr[n];
    int cnt   = deg_scr[n];
    int k = lane & 15;
    int half = lane >> 4;

    float acc = 0.f;
    for (int base = 0; base < cnt; base += 32) {
        int rem = cnt - base;
        int m = rem < 32 ? rem : 32;
        int sv = (lane < m) ? elist_scr[start + base + lane] : 0;

        int nfull = m >> 3;                  // uniform across warp
        for (int j = 0; j < nfull; ++j) {
            int i = 8 * j + half;
            int s0 = __shfl_sync(0xffffffffu, sv, i);
            int s1 = __shfl_sync(0xffffffffu, sv, i + 2);
            int s2 = __shfl_sync(0xffffffffu, sv, i + 4);
            int s3 = __shfl_sync(0xffffffffu, sv, i + 6);
            float v0 = g_scr[(size_t)s0 * HID + k];
            float v1 = g_scr[(size_t)s1 * HID + k];
            float v2 = g_scr[(size_t)s2 * HID + k];
            float v3 = g_scr[(size_t)s3 * HID + k];
            acc += (v0 + v1) + (v2 + v3);
        }
        int itail = 8 * nfull + half;        // uniform 4-iteration tail, predicated
        #pragma unroll
        for (int t = 0; t < 4; ++t) {
            int i = itail + 2 * t;
            int s = __shfl_sync(0xffffffffu, sv, i & 31);
            if (i < m) acc += g_scr[(size_t)s * HID + k];
        }
    }
    acc += __shfl_down_sync(0xffffffffu, acc, 16);

    float dd = dis_scr[n];
    float h2 = 0.f;
    if (lane < 16) {
        float gk = g_scr[(size_t)n * HID + k];
        float h = fmaxf(fmaf(dd, acc + gk, __ldg(&b1[k])), 0.f);
        h2 = h * __ldg(&W2[k]);
    }
    #pragma unroll
    for (int off = 8; off; off >>= 1) h2 += __shfl_down_sync(0xffffffffu, h2, off);

    __shared__ float part[8];
    if (lane == 0) part[wid] = h2 * dd * (c_scr[n] + dd);
    __syncthreads();
    if (threadIdx.x == 0) {
        float t = 0.f;
        #pragma unroll
        for (int w = 0; w < 8; ++w) t += part[w];
        atomicAdd(&score_scr[gidx], t);
    }
}

// -------- softmax over 5 graph scores --------
__global__ void softmax_kernel(const float* __restrict__ b2, float* __restrict__ out) {
    if (threadIdx.x == 0) {
        float s[NG], m = -1e30f;
        for (int g = 0; g < NG; ++g) {
            s[g] = score_scr[g] * (1.0f / (float)NNODE) + b2[0];
            m = fmaxf(m, s[g]);
        }
        float sum = 0.f, e[NG];
        for (int g = 0; g < NG; ++g) { e[g] = expf(s[g] - m); sum += e[g]; }
        for (int g = 0; g < NG; ++g) out[g] = e[g] / sum;
    }
}

extern "C" void kernel_launch(void* const* d_in, const int* in_sizes, int n_in,
                              void* d_out, int out_size) {
    const float* emb = (const float*)d_in[0];
    const void*  ei  = d_in[1];
    const float* W1  = (const float*)d_in[2];
    const float* b1  = (const float*)d_in[3];
    const float* W2  = (const float*)d_in[4];
    const float* b2  = (const float*)d_in[5];
    float* out = (float*)d_out;

    cudaFuncSetAttribute((const void*)gemm_kernel,
                         cudaFuncAttributeMaxDynamicSharedMemorySize, GEMM_SMEM);

    detect_kernel<<<1, 32>>>(ei);
    init_kernel<<<(TOT + 255) / 256, 256>>>();

    dim3 eg((NEDGE / 4 + 255) / 256, NG);
    deg_kernel<<<eg, 256>>>(ei);

    scan_a_kernel<<<SCAN_BLK, 256>>>();
    scan_b_kernel<<<1, 512>>>();
    scan_c_kernel<<<SCAN_BLK, 256>>>();

    fill_kernel<<<eg, 256>>>(ei);

    gemm_kernel<<<(TOT + 511) / 512, 256, GEMM_SMEM>>>(emb, W1);

    gather_kernel<<<TOT / 8, 256>>>(b1, W2);

    softmax_kernel<<<1, 32>>>(b2, out);
}

// round 3
// speedup vs baseline: 1.1664x; 1.1257x over previous
#include <cuda_runtime.h>

#define NNODE   100000
#define NEDGE   3200000
#define DIM     300
#define HID     16
#define NG      5
#define TOT     (NG*NNODE)      // 500000
#define TOTEDGE (NG*NEDGE)      // 16000000
#define CAP     80              // bucket slots per node; P(deg>=80)~5e-13 per node

// -------- scratch (no allocations allowed; __device__ globals) --------
__device__ __align__(16) float g_scr[TOT*HID];     // (emb@W1), then *dis[n] after scale
__device__ int   bucket_scr[TOT*CAP];              // 160MB: src lists grouped by dst
__device__ int   cnt_scr[TOT];                     // in-degree / bucket fill count
__device__ float dis_scr[TOT];
__device__ float f_scr[TOT];                       // f[n] = z[n]*dis[n]
__device__ float score_scr[NG];
__device__ int   d_is64;

// -------- detect whether edge_index is int64 or int32 (jax x64 trap) --------
__global__ void detect_kernel(const void* ei) {
    if (threadIdx.x == 0) {
        const unsigned long long* p = (const unsigned long long*)ei;
        int ok = 1;
        for (int i = 0; i < 64; ++i)
            if (p[i] >> 32) ok = 0;   // int32 data -> high word is another index (!=0 w.h.p.)
        d_is64 = ok;
    }
}

// -------- init: zero the atomically-updated accumulators --------
__global__ void init_kernel() {
    int i = blockIdx.x * blockDim.x + threadIdx.x;
    if (i < TOT) cnt_scr[i] = 0;
    if (i < NG)  score_scr[i] = 0.f;
}

// -------- GEMM (raw): g[n][k] = sum_j emb[n][j]*W1[j][k] --------
#define JC 30
#define SA_STRIDE 513
#define SW_FLOATS (DIM*HID)          // 4800
#define SA_FLOATS (JC*SA_STRIDE)     // 15390
#define GEMM_SMEM ((SW_FLOATS + SA_FLOATS) * 4)

#define STEP(ACC, A) \
    ACC[0]=fmaf(A,w0.x,ACC[0]);  ACC[1]=fmaf(A,w0.y,ACC[1]);  \
    ACC[2]=fmaf(A,w0.z,ACC[2]);  ACC[3]=fmaf(A,w0.w,ACC[3]);  \
    ACC[4]=fmaf(A,w1.x,ACC[4]);  ACC[5]=fmaf(A,w1.y,ACC[5]);  \
    ACC[6]=fmaf(A,w1.z,ACC[6]);  ACC[7]=fmaf(A,w1.w,ACC[7]);  \
    ACC[8]=fmaf(A,w2.x,ACC[8]);  ACC[9]=fmaf(A,w2.y,ACC[9]);  \
    ACC[10]=fmaf(A,w2.z,ACC[10]);ACC[11]=fmaf(A,w2.w,ACC[11]);\
    ACC[12]=fmaf(A,w3.x,ACC[12]);ACC[13]=fmaf(A,w3.y,ACC[13]);\
    ACC[14]=fmaf(A,w3.z,ACC[14]);ACC[15]=fmaf(A,w3.w,ACC[15]);

__global__ void __launch_bounds__(256) gemm_kernel(const float* __restrict__ emb,
                                                   const float* __restrict__ W1) {
    extern __shared__ float sm[];
    float* sW = sm;                // 4800 floats
    float* sA = sm + SW_FLOATS;    // [JC][513]
    int tid = threadIdx.x;
    int nbase = blockIdx.x * 512;

    for (int idx = tid; idx < SW_FLOATS; idx += 256) sW[idx] = W1[idx];

    float acc0[16], acc1[16];
    #pragma unroll
    for (int k = 0; k < 16; ++k) { acc0[k] = 0.f; acc1[k] = 0.f; }

    for (int c = 0; c < 10; ++c) {
        int j0 = c * JC;
        __syncthreads();
        #pragma unroll
        for (int it = 0; it < 30; ++it) {
            int idx = it * 256 + tid;
            int n = idx / 15;
            int jp = idx - n * 15;
            int gn = nbase + n;
            float2 v = make_float2(0.f, 0.f);
            if (gn < TOT)
                v = *(const float2*)(emb + (size_t)gn * DIM + j0 + 2 * jp);
            sA[(2 * jp)     * SA_STRIDE + n] = v.x;
            sA[(2 * jp + 1) * SA_STRIDE + n] = v.y;
        }
        __syncthreads();
        #pragma unroll
        for (int jl = 0; jl < JC; ++jl) {
            float a0 = sA[jl * SA_STRIDE + tid];
            float a1 = sA[jl * SA_STRIDE + 256 + tid];
            const float4* wr = (const float4*)(sW + (j0 + jl) * HID);
            float4 w0 = wr[0], w1 = wr[1], w2 = wr[2], w3 = wr[3];
            STEP(acc0, a0)
            STEP(acc1, a1)
        }
    }

    int gn0 = nbase + tid;
    int gn1 = nbase + 256 + tid;
    if (gn0 < TOT) {
        float4* o = (float4*)(g_scr + (size_t)gn0 * HID);
        o[0] = make_float4(acc0[0],  acc0[1],  acc0[2],  acc0[3]);
        o[1] = make_float4(acc0[4],  acc0[5],  acc0[6],  acc0[7]);
        o[2] = make_float4(acc0[8],  acc0[9],  acc0[10], acc0[11]);
        o[3] = make_float4(acc0[12], acc0[13], acc0[14], acc0[15]);
    }
    if (gn1 < TOT) {
        float4* o = (float4*)(g_scr + (size_t)gn1 * HID);
        o[0] = make_float4(acc1[0],  acc1[1],  acc1[2],  acc1[3]);
        o[1] = make_float4(acc1[4],  acc1[5],  acc1[6],  acc1[7]);
        o[2] = make_float4(acc1[8],  acc1[9],  acc1[10], acc1[11]);
        o[3] = make_float4(acc1[12], acc1[13], acc1[14], acc1[15]);
    }
}

// -------- bucket fill: one atomic per edge, direct scatter --------
__global__ void fill_kernel(const void* __restrict__ ei) {
    int e0 = (blockIdx.x * blockDim.x + threadIdx.x) * 4;
    if (e0 >= NEDGE) return;
    int gy = blockIdx.y;
    int nb = gy * NNODE;
    int s[4], d[4];
    if (d_is64) {
        const long long* base = (const long long*)ei + (long long)gy * 2 * NEDGE;
        longlong2 sa = *(const longlong2*)(base + e0);
        longlong2 sb = *(const longlong2*)(base + e0 + 2);
        longlong2 da = *(const longlong2*)(base + NEDGE + e0);
        longlong2 db = *(const longlong2*)(base + NEDGE + e0 + 2);
        s[0]=(int)sa.x; s[1]=(int)sa.y; s[2]=(int)sb.x; s[3]=(int)sb.y;
        d[0]=(int)da.x; d[1]=(int)da.y; d[2]=(int)db.x; d[3]=(int)db.y;
    } else {
        const int* base = (const int*)ei + (long long)gy * 2 * NEDGE;
        int4 sv = *(const int4*)(base + e0);
        int4 dv = *(const int4*)(base + NEDGE + e0);
        s[0]=sv.x; s[1]=sv.y; s[2]=sv.z; s[3]=sv.w;
        d[0]=dv.x; d[1]=dv.y; d[2]=dv.z; d[3]=dv.w;
    }
    #pragma unroll
    for (int r = 0; r < 4; ++r) {
        int ds = nb + d[r];
        int pos = atomicAdd(&cnt_scr[ds], 1);
        if (pos < CAP) bucket_scr[ds * CAP + pos] = nb + s[r];
    }
}

// -------- dis = rsqrt(deg+1) --------
__global__ void dis_kernel() {
    int i = blockIdx.x * blockDim.x + threadIdx.x;
    if (i < TOT) dis_scr[i] = rsqrtf((float)cnt_scr[i] + 1.0f);
}

// -------- scale g by dis[n] (coalesced, thread per float4) --------
__global__ void scale_kernel() {
    int idx = blockIdx.x * blockDim.x + threadIdx.x;   // float4 index
    if (idx >= TOT * 4) return;
    int n = idx >> 2;
    float dd = dis_scr[n];
    float4* p = (float4*)g_scr + idx;
    float4 v = *p;
    v.x *= dd; v.y *= dd; v.z *= dd; v.w *= dd;
    *p = v;
}

// -------- gather + layer1 + layer2 dot; stores f[n], accumulates self term --------
// warp per node; lane = (edge-slot 0..7) x (float4 quarter 0..3); 8 edges per warp step.
__global__ void __launch_bounds__(256) gather_kernel(const float* __restrict__ b1,
                                                     const float* __restrict__ W2) {
    int wid  = threadIdx.x >> 5;
    int lane = threadIdx.x & 31;
    int n = blockIdx.x * 8 + wid;            // 100000 % 8 == 0: blocks never straddle graphs
    int gidx = blockIdx.x / (NNODE / 8);

    int cnt = cnt_scr[n];
    if (cnt > CAP) cnt = CAP;
    int start = n * CAP;
    int q = lane & 3;                        // float4 quarter
    int es = lane >> 2;                      // edge slot within group of 8

    float4 acc = make_float4(0.f, 0.f, 0.f, 0.f);
    for (int base = 0; base < cnt; base += 32) {
        int rem = cnt - base;
        int m = rem < 32 ? rem : 32;
        int sv = (lane < m) ? bucket_scr[start + base + lane] : 0;
        if (m == 32) {
            #pragma unroll
            for (int j = 0; j < 4; ++j) {
                int s = __shfl_sync(0xffffffffu, sv, j * 8 + es);
                float4 v = *((const float4*)(g_scr + (size_t)s * HID) + q);
                acc.x += v.x; acc.y += v.y; acc.z += v.z; acc.w += v.w;
            }
        } else {
            #pragma unroll
            for (int j = 0; j < 4; ++j) {
                int e = j * 8 + es;
                int s = __shfl_sync(0xffffffffu, sv, e);
                if (e < m) {
                    float4 v = *((const float4*)(g_scr + (size_t)s * HID) + q);
                    acc.x += v.x; acc.y += v.y; acc.z += v.z; acc.w += v.w;
                }
            }
        }
    }
    // reduce 8 edge-slots -> slot 0 (lanes 0..3 hold the 4 quarters)
    #pragma unroll
    for (int off = 16; off >= 4; off >>= 1) {
        acc.x += __shfl_down_sync(0xffffffffu, acc.x, off);
        acc.y += __shfl_down_sync(0xffffffffu, acc.y, off);
        acc.z += __shfl_down_sync(0xffffffffu, acc.z, off);
        acc.w += __shfl_down_sync(0xffffffffu, acc.w, off);
    }

    float dd = dis_scr[n];
    float zp = 0.f;
    if (lane < 4) {
        float4 gk = *((const float4*)(g_scr + (size_t)n * HID) + q);
        float4 bb = __ldg((const float4*)b1 + q);
        float4 ww = __ldg((const float4*)W2 + q);
        float h0 = fmaxf(fmaf(dd, acc.x + gk.x, bb.x), 0.f);
        float h1 = fmaxf(fmaf(dd, acc.y + gk.y, bb.y), 0.f);
        float h2 = fmaxf(fmaf(dd, acc.z + gk.z, bb.z), 0.f);
        float h3 = fmaxf(fmaf(dd, acc.w + gk.w, bb.w), 0.f);
        zp = h0 * ww.x + h1 * ww.y + h2 * ww.z + h3 * ww.w;
    }
    zp += __shfl_down_sync(0xffffffffu, zp, 2);
    zp += __shfl_down_sync(0xffffffffu, zp, 1);

    __shared__ float part[8];
    if (lane == 0) {
        float f = zp * dd;                   // f[n] = z[n]*dis[n]
        f_scr[n] = f;
        part[wid] = f * dd;                  // self-loop term f[n]*dis[n]
    }
    __syncthreads();
    if (threadIdx.x == 0) {
        float t = 0.f;
        #pragma unroll
        for (int w = 0; w < 8; ++w) t += part[w];
        atomicAdd(&score_scr[gidx], t);
    }
}

// -------- edge score: sum_d dis[d] * sum_{s in bucket[d]} f[s] --------
__global__ void __launch_bounds__(256) edge_score_kernel() {
    int wid  = threadIdx.x >> 5;
    int lane = threadIdx.x & 31;
    int n = blockIdx.x * 8 + wid;
    int gidx = blockIdx.x / (NNODE / 8);

    int cnt = cnt_scr[n];
    if (cnt > CAP) cnt = CAP;
    int start = n * CAP;

    float acc = 0.f;
    for (int base = lane; base < cnt; base += 32) {
        int s = bucket_scr[start + base];
        acc += f_scr[s];
    }
    #pragma unroll
    for (int off = 16; off; off >>= 1)
        acc += __shfl_down_sync(0xffffffffu, acc, off);

    __shared__ float part[8];
    if (lane == 0) part[wid] = acc * dis_scr[n];
    __syncthreads();
    if (threadIdx.x == 0) {
        float t = 0.f;
        #pragma unroll
        for (int w = 0; w < 8; ++w) t += part[w];
        atomicAdd(&score_scr[gidx], t);
    }
}

// -------- softmax over 5 graph scores --------
__global__ void softmax_kernel(const float* __restrict__ b2, float* __restrict__ out) {
    if (threadIdx.x == 0) {
        float s[NG], m = -1e30f;
        for (int g = 0; g < NG; ++g) {
            s[g] = score_scr[g] * (1.0f / (float)NNODE) + b2[0];
            m = fmaxf(m, s[g]);
        }
        float sum = 0.f, e[NG];
        for (int g = 0; g < NG; ++g) { e[g] = expf(s[g] - m); sum += e[g]; }
        for (int g = 0; g < NG; ++g) out[g] = e[g] / sum;
    }
}

extern "C" void kernel_launch(void* const* d_in, const int* in_sizes, int n_in,
                              void* d_out, int out_size) {
    const float* emb = (const float*)d_in[0];
    const void*  ei  = d_in[1];
    const float* W1  = (const float*)d_in[2];
    const float* b1  = (const float*)d_in[3];
    const float* W2  = (const float*)d_in[4];
    const float* b2  = (const float*)d_in[5];
    float* out = (float*)d_out;

    cudaFuncSetAttribute((const void*)gemm_kernel,
                         cudaFuncAttributeMaxDynamicSharedMemorySize, GEMM_SMEM);

    detect_kernel<<<1, 32>>>(ei);                               // 1
    init_kernel<<<(TOT + 255) / 256, 256>>>();                  // 2
    gemm_kernel<<<(TOT + 511) / 512, 256, GEMM_SMEM>>>(emb, W1);// 3
    dim3 eg((NEDGE / 4 + 255) / 256, NG);
    fill_kernel<<<eg, 256>>>(ei);                               // 4  <- profiled launch
    dis_kernel<<<(TOT + 255) / 256, 256>>>();                   // 5
    scale_kernel<<<(TOT * 4 + 255) / 256, 256>>>();             // 6
    gather_kernel<<<TOT / 8, 256>>>(b1, W2);                    // 7
    edge_score_kernel<<<TOT / 8, 256>>>();                      // 8
    softmax_kernel<<<1, 32>>>(b2, out);                         // 9
}

// round 4
// speedup vs baseline: 1.2414x; 1.0643x over previous
#include <cuda_runtime.h>

#define NNODE   100000
#define NEDGE   3200000
#define DIM     300
#define HID     16
#define NG      5
#define TOT     (NG*NNODE)      // 500000
#define TOTEDGE (NG*NEDGE)      // 16000000
#define CAP     80              // bucket slots per node; P(deg>=80)~5e-13 per node

// -------- scratch (no allocations allowed; __device__ globals) --------
__device__ __align__(16) float g_scr[TOT*HID];     // (emb@W1) raw, then *dis[n] in disscale
__device__ int   bucket_scr[TOT*CAP];              // 160MB: src lists grouped by dst
__device__ int   cnt_scr[TOT];                     // in-degree / bucket fill count
__device__ float dis_scr[TOT];
__device__ float f_scr[TOT];                       // f[n] = z[n]*dis[n]
__device__ float score_scr[NG];
__device__ int   d_is64;

// -------- detect int64-vs-int32 edge dtype + zero accumulators (fused) --------
__global__ void detectinit_kernel(const void* ei) {
    int i = blockIdx.x * blockDim.x + threadIdx.x;
    if (i == 0) {
        const unsigned long long* p = (const unsigned long long*)ei;
        int ok = 1;
        for (int t = 0; t < 64; ++t)
            if (p[t] >> 32) ok = 0;   // int32 data -> high word is another index (!=0 w.h.p.)
        d_is64 = ok;
    }
    if (i < TOT) cnt_scr[i] = 0;
    if (i < NG)  score_scr[i] = 0.f;
}

// -------- GEMM (raw): g[n][k] = sum_j emb[n][j]*W1[j][k] --------
#define JC 30
#define SA_STRIDE 513
#define SW_FLOATS (DIM*HID)          // 4800
#define SA_FLOATS (JC*SA_STRIDE)     // 15390
#define GEMM_SMEM ((SW_FLOATS + SA_FLOATS) * 4)

#define STEP(ACC, A) \
    ACC[0]=fmaf(A,w0.x,ACC[0]);  ACC[1]=fmaf(A,w0.y,ACC[1]);  \
    ACC[2]=fmaf(A,w0.z,ACC[2]);  ACC[3]=fmaf(A,w0.w,ACC[3]);  \
    ACC[4]=fmaf(A,w1.x,ACC[4]);  ACC[5]=fmaf(A,w1.y,ACC[5]);  \
    ACC[6]=fmaf(A,w1.z,ACC[6]);  ACC[7]=fmaf(A,w1.w,ACC[7]);  \
    ACC[8]=fmaf(A,w2.x,ACC[8]);  ACC[9]=fmaf(A,w2.y,ACC[9]);  \
    ACC[10]=fmaf(A,w2.z,ACC[10]);ACC[11]=fmaf(A,w2.w,ACC[11]);\
    ACC[12]=fmaf(A,w3.x,ACC[12]);ACC[13]=fmaf(A,w3.y,ACC[13]);\
    ACC[14]=fmaf(A,w3.z,ACC[14]);ACC[15]=fmaf(A,w3.w,ACC[15]);

__global__ void __launch_bounds__(256) gemm_kernel(const float* __restrict__ emb,
                                                   const float* __restrict__ W1) {
    extern __shared__ float sm[];
    float* sW = sm;                // 4800 floats
    float* sA = sm + SW_FLOATS;    // [JC][513]
    int tid = threadIdx.x;
    int nbase = blockIdx.x * 512;

    for (int idx = tid; idx < SW_FLOATS; idx += 256) sW[idx] = W1[idx];

    float acc0[16], acc1[16];
    #pragma unroll
    for (int k = 0; k < 16; ++k) { acc0[k] = 0.f; acc1[k] = 0.f; }

    for (int c = 0; c < 10; ++c) {
        int j0 = c * JC;
        __syncthreads();
        #pragma unroll
        for (int it = 0; it < 30; ++it) {
            int idx = it * 256 + tid;
            int n = idx / 15;
            int jp = idx - n * 15;
            int gn = nbase + n;
            float2 v = make_float2(0.f, 0.f);
            if (gn < TOT)
                v = *(const float2*)(emb + (size_t)gn * DIM + j0 + 2 * jp);
            sA[(2 * jp)     * SA_STRIDE + n] = v.x;
            sA[(2 * jp + 1) * SA_STRIDE + n] = v.y;
        }
        __syncthreads();
        #pragma unroll
        for (int jl = 0; jl < JC; ++jl) {
            float a0 = sA[jl * SA_STRIDE + tid];
            float a1 = sA[jl * SA_STRIDE + 256 + tid];
            const float4* wr = (const float4*)(sW + (j0 + jl) * HID);
            float4 w0 = wr[0], w1 = wr[1], w2 = wr[2], w3 = wr[3];
            STEP(acc0, a0)
            STEP(acc1, a1)
        }
    }

    int gn0 = nbase + tid;
    int gn1 = nbase + 256 + tid;
    if (gn0 < TOT) {
        float4* o = (float4*)(g_scr + (size_t)gn0 * HID);
        o[0] = make_float4(acc0[0],  acc0[1],  acc0[2],  acc0[3]);
        o[1] = make_float4(acc0[4],  acc0[5],  acc0[6],  acc0[7]);
        o[2] = make_float4(acc0[8],  acc0[9],  acc0[10], acc0[11]);
        o[3] = make_float4(acc0[12], acc0[13], acc0[14], acc0[15]);
    }
    if (gn1 < TOT) {
        float4* o = (float4*)(g_scr + (size_t)gn1 * HID);
        o[0] = make_float4(acc1[0],  acc1[1],  acc1[2],  acc1[3]);
        o[1] = make_float4(acc1[4],  acc1[5],  acc1[6],  acc1[7]);
        o[2] = make_float4(acc1[8],  acc1[9],  acc1[10], acc1[11]);
        o[3] = make_float4(acc1[12], acc1[13], acc1[14], acc1[15]);
    }
}

// -------- bucket fill: one atomic per edge, direct scatter --------
__global__ void fill_kernel(const void* __restrict__ ei) {
    int e0 = (blockIdx.x * blockDim.x + threadIdx.x) * 4;
    if (e0 >= NEDGE) return;
    int gy = blockIdx.y;
    int nb = gy * NNODE;
    int s[4], d[4];
    if (d_is64) {
        const long long* base = (const long long*)ei + (long long)gy * 2 * NEDGE;
        longlong2 sa = *(const longlong2*)(base + e0);
        longlong2 sb = *(const longlong2*)(base + e0 + 2);
        longlong2 da = *(const longlong2*)(base + NEDGE + e0);
        longlong2 db = *(const longlong2*)(base + NEDGE + e0 + 2);
        s[0]=(int)sa.x; s[1]=(int)sa.y; s[2]=(int)sb.x; s[3]=(int)sb.y;
        d[0]=(int)da.x; d[1]=(int)da.y; d[2]=(int)db.x; d[3]=(int)db.y;
    } else {
        const int* base = (const int*)ei + (long long)gy * 2 * NEDGE;
        int4 sv = *(const int4*)(base + e0);
        int4 dv = *(const int4*)(base + NEDGE + e0);
        s[0]=sv.x; s[1]=sv.y; s[2]=sv.z; s[3]=sv.w;
        d[0]=dv.x; d[1]=dv.y; d[2]=dv.z; d[3]=dv.w;
    }
    #pragma unroll
    for (int r = 0; r < 4; ++r) {
        int ds = nb + d[r];
        int pos = atomicAdd(&cnt_scr[ds], 1);
        if (pos < CAP) bucket_scr[ds * CAP + pos] = nb + s[r];
    }
}

// -------- fused: dis = rsqrt(deg+1); g *= dis (thread per float4) --------
__global__ void disscale_kernel() {
    int idx = blockIdx.x * blockDim.x + threadIdx.x;   // float4 index
    if (idx >= TOT * 4) return;
    int n = idx >> 2;
    float dd = rsqrtf((float)cnt_scr[n] + 1.0f);
    if ((idx & 3) == 0) dis_scr[n] = dd;
    float4* p = (float4*)g_scr + idx;
    float4 v = *p;
    v.x *= dd; v.y *= dd; v.z *= dd; v.w *= dd;
    *p = v;
}

// -------- gather + layer1 + layer2 dot; stores f[n], accumulates self term --------
// warp per node; lane = (edge-slot 0..7) x (float4 quarter 0..3); 8 edges per warp step.
__global__ void __launch_bounds__(256) gather_kernel(const float* __restrict__ b1,
                                                     const float* __restrict__ W2) {
    int wid  = threadIdx.x >> 5;
    int lane = threadIdx.x & 31;
    int n = blockIdx.x * 8 + wid;            // 100000 % 8 == 0: blocks never straddle graphs
    int gidx = blockIdx.x / (NNODE / 8);

    int cnt = cnt_scr[n];
    if (cnt > CAP) cnt = CAP;
    int start = n * CAP;
    int q = lane & 3;                        // float4 quarter
    int es = lane >> 2;                      // edge slot within group of 8

    float4 acc = make_float4(0.f, 0.f, 0.f, 0.f);
    for (int base = 0; base < cnt; base += 32) {
        int rem = cnt - base;
        int m = rem < 32 ? rem : 32;
        int sv = (lane < m) ? bucket_scr[start + base + lane] : 0;
        if (m == 32) {
            #pragma unroll
            for (int j = 0; j < 4; ++j) {
                int s = __shfl_sync(0xffffffffu, sv, j * 8 + es);
                float4 v = *((const float4*)(g_scr + (size_t)s * HID) + q);
                acc.x += v.x; acc.y += v.y; acc.z += v.z; acc.w += v.w;
            }
        } else {
            #pragma unroll
            for (int j = 0; j < 4; ++j) {
                int e = j * 8 + es;
                int s = __shfl_sync(0xffffffffu, sv, e);
                if (e < m) {
                    float4 v = *((const float4*)(g_scr + (size_t)s * HID) + q);
                    acc.x += v.x; acc.y += v.y; acc.z += v.z; acc.w += v.w;
                }
            }
        }
    }
    // reduce 8 edge-slots -> slot 0 (lanes 0..3 hold the 4 quarters)
    #pragma unroll
    for (int off = 16; off >= 4; off >>= 1) {
        acc.x += __shfl_down_sync(0xffffffffu, acc.x, off);
        acc.y += __shfl_down_sync(0xffffffffu, acc.y, off);
        acc.z += __shfl_down_sync(0xffffffffu, acc.z, off);
        acc.w += __shfl_down_sync(0xffffffffu, acc.w, off);
    }

    float dd = dis_scr[n];
    float zp = 0.f;
    if (lane < 4) {
        float4 gk = *((const float4*)(g_scr + (size_t)n * HID) + q);
        float4 bb = __ldg((const float4*)b1 + q);
        float4 ww = __ldg((const float4*)W2 + q);
        float h0 = fmaxf(fmaf(dd, acc.x + gk.x, bb.x), 0.f);
        float h1 = fmaxf(fmaf(dd, acc.y + gk.y, bb.y), 0.f);
        float h2 = fmaxf(fmaf(dd, acc.z + gk.z, bb.z), 0.f);
        float h3 = fmaxf(fmaf(dd, acc.w + gk.w, bb.w), 0.f);
        zp = h0 * ww.x + h1 * ww.y + h2 * ww.z + h3 * ww.w;
    }
    zp += __shfl_down_sync(0xffffffffu, zp, 2);
    zp += __shfl_down_sync(0xffffffffu, zp, 1);

    __shared__ float part[8];
    if (lane == 0) {
        float f = zp * dd;                   // f[n] = z[n]*dis[n]
        f_scr[n] = f;
        part[wid] = f * dd;                  // self-loop term f[n]*dis[n]
    }
    __syncthreads();
    if (threadIdx.x == 0) {
        float t = 0.f;
        #pragma unroll
        for (int w = 0; w < 8; ++w) t += part[w];
        atomicAdd(&score_scr[gidx], t);
    }
}

// -------- edge score: sum_d dis[d] * sum_{s in bucket[d]} f[s] --------
__global__ void __launch_bounds__(256) edge_score_kernel() {
    int wid  = threadIdx.x >> 5;
    int lane = threadIdx.x & 31;
    int n = blockIdx.x * 8 + wid;
    int gidx = blockIdx.x / (NNODE / 8);

    int cnt = cnt_scr[n];
    if (cnt > CAP) cnt = CAP;
    int start = n * CAP;

    float acc = 0.f;
    for (int base = lane; base < cnt; base += 32) {
        int s = bucket_scr[start + base];
        acc += f_scr[s];
    }
    #pragma unroll
    for (int off = 16; off; off >>= 1)
        acc += __shfl_down_sync(0xffffffffu, acc, off);

    __shared__ float part[8];
    if (lane == 0) part[wid] = acc * dis_scr[n];
    __syncthreads();
    if (threadIdx.x == 0) {
        float t = 0.f;
        #pragma unroll
        for (int w = 0; w < 8; ++w) t += part[w];
        atomicAdd(&score_scr[gidx], t);
    }
}

// -------- softmax over 5 graph scores --------
__global__ void softmax_kernel(const float* __restrict__ b2, float* __restrict__ out) {
    if (threadIdx.x == 0) {
        float s[NG], m = -1e30f;
        for (int g = 0; g < NG; ++g) {
            s[g] = score_scr[g] * (1.0f / (float)NNODE) + b2[0];
            m = fmaxf(m, s[g]);
        }
        float sum = 0.f, e[NG];
        for (int g = 0; g < NG; ++g) { e[g] = expf(s[g] - m); sum += e[g]; }
        for (int g = 0; g < NG; ++g) out[g] = e[g] / sum;
    }
}

extern "C" void kernel_launch(void* const* d_in, const int* in_sizes, int n_in,
                              void* d_out, int out_size) {
    const float* emb = (const float*)d_in[0];
    const void*  ei  = d_in[1];
    const float* W1  = (const float*)d_in[2];
    const float* b1  = (const float*)d_in[3];
    const float* W2  = (const float*)d_in[4];
    const float* b2  = (const float*)d_in[5];
    float* out = (float*)d_out;

    // one-time host-side resources (no device allocations)
    static cudaStream_t side = nullptr;
    static cudaEvent_t evFork = nullptr, evJoin = nullptr;
    if (!side) {
        cudaStreamCreateWithFlags(&side, cudaStreamNonBlocking);
        cudaEventCreateWithFlags(&evFork, cudaEventDisableTiming);
        cudaEventCreateWithFlags(&evJoin, cudaEventDisableTiming);
        cudaFuncSetAttribute((const void*)gemm_kernel,
                             cudaFuncAttributeMaxDynamicSharedMemorySize, GEMM_SMEM);
    }

    detectinit_kernel<<<(TOT + 255) / 256, 256>>>(ei);              // 1 (stream 0)

    // fork: gemm runs on side stream, concurrent with fill on stream 0
    cudaEventRecord(evFork, 0);
    cudaStreamWaitEvent(side, evFork, 0);
    gemm_kernel<<<(TOT + 511) / 512, 256, GEMM_SMEM, side>>>(emb, W1);  // 2 (side)
    cudaEventRecord(evJoin, side);

    dim3 eg((NEDGE / 4 + 255) / 256, NG);
    fill_kernel<<<eg, 256>>>(ei);                                   // 3 (stream 0)

    cudaStreamWaitEvent(0, evJoin, 0);                              // join

    disscale_kernel<<<(TOT * 4 + 255) / 256, 256>>>();              // 4
    gather_kernel<<<TOT / 8, 256>>>(b1, W2);                        // 5
    edge_score_kernel<<<TOT / 8, 256>>>();                          // 6
    softmax_kernel<<<1, 32>>>(b2, out);                             // 7
}